// round 5
// baseline (speedup 1.0000x reference)
#include <cuda_runtime.h>
#include <cuda_fp16.h>
#include <cstdint>

#define Cc   256
#define Bn   8
#define Hh   128
#define Ww   128
#define NWw  512
#define HW   (Hh*Ww)
#define NPIX (Bn*HW)          // 131072
#define EPSf 1e-5f

// ---- scratch (__device__ globals; no allocations allowed) -------------------
__device__ float  g_ps [Cc*Bn];
__device__ float  g_ps2[Cc*Bn];
__device__ float  g_scale[Cc];
__device__ float  g_shift[Cc];
__device__ __half g_w1h[Cc*NWw];                 // [c][j] K-major A operand
__device__ __half g_y[(size_t)NPIX * NWw];       // [pixel][j] K-major B operand

__device__ __forceinline__ uint32_t smem_u32(const void* p) {
    uint32_t a;
    asm("{ .reg .u64 t; cvta.to.shared.u64 t, %1; cvt.u32.u64 %0, t; }"
        : "=r"(a) : "l"(p));
    return a;
}

// ---------------------------------------------------------------------------
// Kernel 1: per-(c,b) partial sums (deterministic 2-stage stats)
// ---------------------------------------------------------------------------
__global__ __launch_bounds__(256) void stats_part(const float* __restrict__ x) {
    int c = blockIdx.x, b = blockIdx.y, tid = threadIdx.x;
    const float4* p = (const float4*)(x + ((size_t)(b * Cc + c)) * HW);
    float s = 0.f, s2 = 0.f;
    #pragma unroll 4
    for (int i = tid; i < HW / 4; i += 256) {
        float4 v = __ldg(p + i);
        s  += v.x + v.y + v.z + v.w;
        s2 += v.x*v.x + v.y*v.y + v.z*v.z + v.w*v.w;
    }
    __shared__ float sh[256], sh2[256];
    sh[tid] = s; sh2[tid] = s2;
    __syncthreads();
    for (int off = 128; off > 0; off >>= 1) {
        if (tid < off) { sh[tid] += sh[tid+off]; sh2[tid] += sh2[tid+off]; }
        __syncthreads();
    }
    if (tid == 0) { g_ps[c*Bn + b] = sh[0]; g_ps2[c*Bn + b] = sh2[0]; }
}

__global__ void finalize_stats(const float* __restrict__ gamma,
                               const float* __restrict__ beta) {
    int c = threadIdx.x;
    float s = 0.f, s2 = 0.f;
    #pragma unroll
    for (int b = 0; b < Bn; b++) { s += g_ps[c*Bn+b]; s2 += g_ps2[c*Bn+b]; }
    float n = (float)(Bn * HW);
    float mean = s / n;
    float var  = s2 / n - mean * mean;
    float sc   = gamma[c] * rsqrtf(var + EPSf);
    g_scale[c] = sc;
    g_shift[c] = beta[c] - mean * sc;
}

__global__ void w1half(const float* __restrict__ w1) {
    int i = blockIdx.x * 256 + threadIdx.x;
    g_w1h[i] = __float2half_rn(w1[i]);
}

// ---------------------------------------------------------------------------
// Kernel 2 (v3): BN -> depthwise 3x3 -> relu -> fp16 y[pixel][j]
// Block: 4 input channels (8 j) x 8-row strip x 128 cols. 3 CTAs/SM target.
// ---------------------------------------------------------------------------
__global__ __launch_bounds__(256, 3)
void dw_kernel(const float* __restrict__ x, const float* __restrict__ lbp) {
    // col c at [4+c]; taps span [3..132]; [3],[132] zeroed.
    __shared__ float xs[4][10][136];          // 21.25 KB
    __shared__ float lw[8][9];

    const int tid   = threadIdx.x;
    const int chunk = blockIdx.x;             // 0..63 (4-channel chunks)
    const int h0    = blockIdx.y * 8;
    const int b     = blockIdx.z;
    const int cbase = chunk * 4;
    const int jbase = chunk * 8;

    if (tid < 40) {
        int ci = tid / 10, rr = tid - ci * 10;
        xs[ci][rr][3]   = 0.f;
        xs[ci][rr][132] = 0.f;
    }
    if (tid < 72) ((float*)lw)[tid] = __ldg(lbp + jbase * 9 + tid);

    // tile: 4 ch x 10 rows x 32 float4, normalized (OOB rows -> 0)
    #pragma unroll
    for (int i = 0; i < 5; i++) {
        int idx = tid + i * 256;              // 0..1279
        int ci  = idx / 320;
        int rem = idx - ci * 320;
        int rr  = rem >> 5, q = rem & 31;
        int hh  = h0 - 1 + rr;
        float4 w = make_float4(0.f, 0.f, 0.f, 0.f);
        if ((unsigned)hh < (unsigned)Hh) {
            float sc = g_scale[cbase + ci];
            float sf = g_shift[cbase + ci];
            float4 v = __ldg((const float4*)(x + ((size_t)(b * Cc + cbase + ci)) * HW)
                             + hh * 32 + q);
            w.x = fmaf(v.x, sc, sf);
            w.y = fmaf(v.y, sc, sf);
            w.z = fmaf(v.z, sc, sf);
            w.w = fmaf(v.w, sc, sf);
        }
        *(float4*)&xs[ci][rr][4 + 4 * q] = w;
    }
    __syncthreads();

    const int p  = tid & 127;
    const int jh = tid >> 7;                  // selects ci pair {2jh, 2jh+1}

    uint32_t opack[8][2];                     // [row][cidx] half2 (j pair)

    #pragma unroll
    for (int cidx = 0; cidx < 2; cidx++) {
        const int ci = jh * 2 + cidx;
        const int jl = ci * 2;
        float w0[9], w1w[9];
        #pragma unroll
        for (int t = 0; t < 9; t++) { w0[t] = lw[jl][t]; w1w[t] = lw[jl + 1][t]; }

        float a0 = xs[ci][0][3 + p], a1 = xs[ci][0][4 + p], a2 = xs[ci][0][5 + p];
        float b0 = xs[ci][1][3 + p], b1v = xs[ci][1][4 + p], b2 = xs[ci][1][5 + p];
        #pragma unroll
        for (int r = 0; r < 8; r++) {
            float c0 = xs[ci][r + 2][3 + p];
            float c1 = xs[ci][r + 2][4 + p];
            float c2 = xs[ci][r + 2][5 + p];
            float s0, s1;
            s0 = w0[0]*a0;            s1 = w1w[0]*a0;
            s0 = fmaf(w0[1],a1,s0);   s1 = fmaf(w1w[1],a1,s1);
            s0 = fmaf(w0[2],a2,s0);   s1 = fmaf(w1w[2],a2,s1);
            s0 = fmaf(w0[3],b0,s0);   s1 = fmaf(w1w[3],b0,s1);
            s0 = fmaf(w0[4],b1v,s0);  s1 = fmaf(w1w[4],b1v,s1);
            s0 = fmaf(w0[5],b2,s0);   s1 = fmaf(w1w[5],b2,s1);
            s0 = fmaf(w0[6],c0,s0);   s1 = fmaf(w1w[6],c0,s1);
            s0 = fmaf(w0[7],c1,s0);   s1 = fmaf(w1w[7],c1,s1);
            s0 = fmaf(w0[8],c2,s0);   s1 = fmaf(w1w[8],c2,s1);
            __half2 hp = __floats2half2_rn(fmaxf(s0, 0.f), fmaxf(s1, 0.f));
            opack[r][cidx] = *(uint32_t*)&hp;
            a0 = b0; a1 = b1v; a2 = b2;
            b0 = c0; b1v = c1; b2 = c2;
        }
    }

    // 8B stores: j range jbase + jh*4 .. +3 (contiguous)
    __half* yb = g_y + ((size_t)(b * Hh + h0) * Ww + p) * NWw + jbase + jh * 4;
    #pragma unroll
    for (int r = 0; r < 8; r++) {
        uint2 v = make_uint2(opack[r][0], opack[r][1]);
        *(uint2*)(yb + (size_t)r * Ww * NWw) = v;
    }
}

// ---------------------------------------------------------------------------
// Kernel 3 (v2): HMMA GEMM, full M=256 per block (y read ONCE from DRAM)
// Block: 512 threads (16 warps, 4x4), tile 256(M) x 128(N), K=512 in 8x64.
// 2-stage cp.async double buffer.
// ---------------------------------------------------------------------------
#define STG_BYTES 49152   // per stage: A 32KB (256x128B) + B 16KB (128x128B)

__global__ __launch_bounds__(512, 1)
void gemm_kernel(const float* __restrict__ x, const float* __restrict__ b1,
                 float* __restrict__ out) {
    extern __shared__ __align__(1024) char dsm[];
    const uint32_t s0 = smem_u32(dsm);

    const int tid  = threadIdx.x;
    const int wid  = tid >> 5, lane = tid & 31;
    const int wm   = wid >> 2;                 // 0..3 (M)
    const int wn   = wid & 3;                  // 0..3 (N)
    const size_t p0 = (size_t)blockIdx.x * 128;

    float acc[4][4][4];
    #pragma unroll
    for (int mi = 0; mi < 4; mi++)
        #pragma unroll
        for (int ni = 0; ni < 4; ni++)
            #pragma unroll
            for (int q = 0; q < 4; q++) acc[mi][ni][q] = 0.f;

    const int lrow = tid >> 3, lu = tid & 7;   // fill coords

    auto fill = [&](int st, int kc) {
        const uint32_t sA = s0 + st * STG_BYTES;
        const uint32_t sB = sA + 32768;
        const int k0 = kc * 64;
        #pragma unroll
        for (int i = 0; i < 4; i++) {          // A: 256 rows
            int row = lrow + i * 64;
            uint32_t sw = ((lu ^ (row & 7)) << 4) + row * 128;
            const __half* srcA = g_w1h + (size_t)row * NWw + k0 + lu * 8;
            asm volatile("cp.async.cg.shared.global [%0], [%1], 16;"
                         :: "r"(sA + sw), "l"(srcA));
        }
        #pragma unroll
        for (int i = 0; i < 2; i++) {          // B: 128 rows
            int row = lrow + i * 64;
            uint32_t sw = ((lu ^ (row & 7)) << 4) + row * 128;
            const __half* srcB = g_y + (p0 + row) * NWw + k0 + lu * 8;
            asm volatile("cp.async.cg.shared.global [%0], [%1], 16;"
                         :: "r"(sB + sw), "l"(srcB));
        }
        asm volatile("cp.async.commit_group;");
    };

    fill(0, 0);
    for (int kc = 0; kc < 8; kc++) {
        if (kc < 7) fill((kc + 1) & 1, kc + 1);
        if (kc < 7) asm volatile("cp.async.wait_group 1;");
        else        asm volatile("cp.async.wait_group 0;");
        __syncthreads();

        const uint32_t sA = s0 + (kc & 1) * STG_BYTES;
        const uint32_t sB = sA + 32768;

        #pragma unroll
        for (int ks = 0; ks < 4; ks++) {
            uint32_t a[4][4], bf[4][2];
            #pragma unroll
            for (int mi = 0; mi < 4; mi++) {
                int row = wm * 64 + mi * 16 + (lane & 15);
                int u   = ks * 2 + (lane >> 4);
                uint32_t ad = sA + row * 128 + ((u ^ (row & 7)) << 4);
                asm volatile(
                    "ldmatrix.sync.aligned.m8n8.x4.shared.b16 {%0,%1,%2,%3}, [%4];"
                    : "=r"(a[mi][0]), "=r"(a[mi][1]), "=r"(a[mi][2]), "=r"(a[mi][3])
                    : "r"(ad));
            }
            #pragma unroll
            for (int ni = 0; ni < 4; ni++) {
                int row = wn * 32 + ni * 8 + (lane & 7);
                int u   = ks * 2 + ((lane >> 3) & 1);
                uint32_t bd = sB + row * 128 + ((u ^ (row & 7)) << 4);
                asm volatile(
                    "ldmatrix.sync.aligned.m8n8.x2.shared.b16 {%0,%1}, [%2];"
                    : "=r"(bf[ni][0]), "=r"(bf[ni][1]) : "r"(bd));
            }
            #pragma unroll
            for (int mi = 0; mi < 4; mi++)
                #pragma unroll
                for (int ni = 0; ni < 4; ni++)
                    asm volatile(
                        "mma.sync.aligned.m16n8k16.row.col.f32.f16.f16.f32 "
                        "{%0,%1,%2,%3}, {%4,%5,%6,%7}, {%8,%9}, {%0,%1,%2,%3};"
                        : "+f"(acc[mi][ni][0]), "+f"(acc[mi][ni][1]),
                          "+f"(acc[mi][ni][2]), "+f"(acc[mi][ni][3])
                        : "r"(a[mi][0]), "r"(a[mi][1]), "r"(a[mi][2]), "r"(a[mi][3]),
                          "r"(bf[ni][0]), "r"(bf[ni][1]));
        }
        __syncthreads();
    }

    // epilogue: + b1[c] + x residual
    const int bb  = (int)(p0 >> 14);
    const int hw0 = (int)(p0 & 16383) + wn * 32 + (lane & 3) * 2;
    #pragma unroll
    for (int mi = 0; mi < 4; mi++) {
        int cb = wm * 64 + mi * 16 + (lane >> 2);
        #pragma unroll
        for (int h = 0; h < 2; h++) {
            int c = cb + h * 8;
            float bias = __ldg(b1 + c);
            size_t base = ((size_t)(bb * Cc + c)) * HW + hw0;
            #pragma unroll
            for (int ni = 0; ni < 4; ni++) {
                size_t o = base + ni * 8;
                float2 xv = *(const float2*)(x + o);
                float2 r;
                r.x = acc[mi][ni][h * 2 + 0] + bias + xv.x;
                r.y = acc[mi][ni][h * 2 + 1] + bias + xv.y;
                *(float2*)(out + o) = r;
            }
        }
    }
}

// ---------------------------------------------------------------------------
extern "C" void kernel_launch(void* const* d_in, const int* in_sizes, int n_in,
                              void* d_out, int out_size) {
    const float* x     = (const float*)d_in[0];
    const float* gamma = (const float*)d_in[1];
    const float* beta  = (const float*)d_in[2];
    const float* lbp   = (const float*)d_in[3];
    const float* w1    = (const float*)d_in[4];
    const float* b1    = (const float*)d_in[5];
    float* out = (float*)d_out;

    static bool attr_done = false;
    if (!attr_done) {
        cudaFuncSetAttribute(gemm_kernel,
                             cudaFuncAttributeMaxDynamicSharedMemorySize,
                             2 * STG_BYTES);
        attr_done = true;
    }

    stats_part<<<dim3(Cc, Bn), 256>>>(x);
    finalize_stats<<<1, Cc>>>(gamma, beta);
    w1half<<<(Cc * NWw) / 256, 256>>>(w1);
    dw_kernel<<<dim3(64, 16, Bn), 256>>>(x, lbp);
    gemm_kernel<<<NPIX / 128, 512, 2 * STG_BYTES>>>(x, b1, out);
}